// round 6
// baseline (speedup 1.0000x reference)
#include <cuda_runtime.h>
#include <cuda_bf16.h>

// XYLoss: out = (S1 / (B*H*W)) * S2
//   S1 = sum over pixels of [(t0+t1)*softplus(s1-s0) - t1*(s1-s0)], s_c = sigmoid(x_c)
//   S2 = sum(object_mask * box_loss_scale)
// Single fused kernel. Warp processes a 64-vector (1KB/array) contiguous tile:
// thread t handles vecs t and t+32 back-to-back -> 1KB DRAM bursts per array
// (vs 512B), improving row-buffer locality.

#define HW_   (1024u * 1024u)
#define B_    16u
#define PIX_  (B_ * HW_)        // 16,777,216 pixels
#define NVEC_ (PIX_ / 4u)       // float4 units
#define NVEC2_ (NVEC_ / 2u)     // vector PAIRS per thread-iteration

constexpr int BLOCKS  = 740;    // 148 SMs * 5 resident blocks (51-reg limit) = one wave
constexpr int THREADS = 256;

__device__ float g_part1[BLOCKS];
__device__ float g_part2[BLOCKS];
__device__ unsigned int g_ticket;   // zero-init at load; last block wraps it back to 0

__device__ __forceinline__ float sigmoid_fast(float x) {
    return __fdividef(1.0f, 1.0f + __expf(-x));   // MUFU.EX2 + MUFU.RCP
}

__device__ __forceinline__ float per_elem(float x0, float x1, float t0, float t1) {
    float s0 = sigmoid_fast(x0);
    float s1 = sigmoid_fast(x1);
    float d  = s1 - s0;                      // in (-1, 1)
    float sp = __logf(1.0f + __expf(d));     // softplus(d), well-conditioned on (-1,1)
    return (t0 + t1) * sp - t1 * d;
}

__device__ __forceinline__ float4 ldcs4(const float* p) {
    return __ldcs(reinterpret_cast<const float4*>(p));
}

__global__ __launch_bounds__(THREADS, 5) void xyloss_fused(
    const float* __restrict__ mask,
    const float* __restrict__ scale,
    const float* __restrict__ pred,
    const float* __restrict__ truth,
    float* __restrict__ out)
{
    float acc1 = 0.0f;
    float acc2 = 0.0f;

    const unsigned int G = (unsigned int)(gridDim.x * blockDim.x);
    for (unsigned int p = blockIdx.x * blockDim.x + threadIdx.x; p < NVEC2_; p += G) {
        // Warp tile: 64 consecutive float4 vectors. Thread t -> vecs t, t+32.
        unsigned int v0   = ((p & ~31u) << 1) + (p & 31u);
        unsigned int idx0 = v0 << 2;                       // float index; pair = idx0, idx0+128
        unsigned int base0 = idx0 + (idx0 & ~(HW_ - 1u));  // = idx0 + b*HW_

        // Same-array loads issued back-to-back: 1KB contiguous warp bursts.
        float4 mA  = ldcs4(mask  + idx0);
        float4 mB  = ldcs4(mask  + idx0 + 128u);
        float4 scA = ldcs4(scale + idx0);
        float4 scB = ldcs4(scale + idx0 + 128u);
        float4 x0A = ldcs4(pred  + base0);
        float4 x0B = ldcs4(pred  + base0 + 128u);
        float4 x1A = ldcs4(pred  + base0 + HW_);
        float4 x1B = ldcs4(pred  + base0 + HW_ + 128u);
        float4 t0A = ldcs4(truth + base0);
        float4 t0B = ldcs4(truth + base0 + 128u);
        float4 t1A = ldcs4(truth + base0 + HW_);
        float4 t1B = ldcs4(truth + base0 + HW_ + 128u);

        acc2 += mA.x * scA.x + mA.y * scA.y + mA.z * scA.z + mA.w * scA.w;
        acc2 += mB.x * scB.x + mB.y * scB.y + mB.z * scB.z + mB.w * scB.w;

        acc1 += per_elem(x0A.x, x1A.x, t0A.x, t1A.x);
        acc1 += per_elem(x0A.y, x1A.y, t0A.y, t1A.y);
        acc1 += per_elem(x0A.z, x1A.z, t0A.z, t1A.z);
        acc1 += per_elem(x0A.w, x1A.w, t0A.w, t1A.w);
        acc1 += per_elem(x0B.x, x1B.x, t0B.x, t1B.x);
        acc1 += per_elem(x0B.y, x1B.y, t0B.y, t1B.y);
        acc1 += per_elem(x0B.z, x1B.z, t0B.z, t1B.z);
        acc1 += per_elem(x0B.w, x1B.w, t0B.w, t1B.w);
    }

    // Warp reduce
    #pragma unroll
    for (int off = 16; off > 0; off >>= 1) {
        acc1 += __shfl_xor_sync(0xFFFFFFFFu, acc1, off);
        acc2 += __shfl_xor_sync(0xFFFFFFFFu, acc2, off);
    }

    // Block reduce across 8 warps
    __shared__ float sh1[THREADS / 32];
    __shared__ float sh2[THREADS / 32];
    __shared__ bool  s_last;
    int wid = threadIdx.x >> 5;
    int lid = threadIdx.x & 31;
    if (lid == 0) { sh1[wid] = acc1; sh2[wid] = acc2; }
    __syncthreads();
    if (threadIdx.x == 0) {
        float b1 = 0.0f, b2 = 0.0f;
        #pragma unroll
        for (int w = 0; w < THREADS / 32; w++) { b1 += sh1[w]; b2 += sh2[w]; }
        g_part1[blockIdx.x] = b1;
        g_part2[blockIdx.x] = b2;
        __threadfence();
        unsigned int t = atomicInc(&g_ticket, BLOCKS - 1);   // wraps to 0 at BLOCKS-1
        s_last = (t == BLOCKS - 1);                          // last arriving block; counter reset
    }
    __syncthreads();

    if (s_last) {
        // Deterministic double-precision combine of all BLOCKS partials.
        double a = 0.0, b = 0.0;
        for (int i = threadIdx.x; i < BLOCKS; i += THREADS) {
            a += (double)g_part1[i];
            b += (double)g_part2[i];
        }
        #pragma unroll
        for (int off = 16; off > 0; off >>= 1) {
            a += __shfl_xor_sync(0xFFFFFFFFu, a, off);
            b += __shfl_xor_sync(0xFFFFFFFFu, b, off);
        }
        __shared__ double da[THREADS / 32];
        __shared__ double db[THREADS / 32];
        if (lid == 0) { da[wid] = a; db[wid] = b; }
        __syncthreads();
        if (threadIdx.x == 0) {
            double A = 0.0, Bb = 0.0;
            #pragma unroll
            for (int w = 0; w < THREADS / 32; w++) { A += da[w]; Bb += db[w]; }
            double loss = A / (double)PIX_;
            out[0] = (float)(loss * Bb);
        }
    }
}

extern "C" void kernel_launch(void* const* d_in, const int* in_sizes, int n_in,
                              void* d_out, int out_size)
{
    const float* mask  = (const float*)d_in[0];
    const float* scale = (const float*)d_in[1];
    const float* pred  = (const float*)d_in[2];
    const float* truth = (const float*)d_in[3];
    float* out = (float*)d_out;

    xyloss_fused<<<BLOCKS, THREADS>>>(mask, scale, pred, truth, out);
}

// round 7
// speedup vs baseline: 1.0320x; 1.0320x over previous
#include <cuda_runtime.h>
#include <cuda_bf16.h>

// XYLoss: out = (S1 / (B*H*W)) * S2
//   S1 = sum over pixels of [(t0+t1)*softplus(d) - t1*d], d = sigmoid(x1)-sigmoid(x0)
//   S2 = sum(object_mask * box_loss_scale)
// sigmoid difference via HW tanh: d = 0.5*(tanh(x1/2) - tanh(x0/2))
//   -> 4 MUFU/pixel (2 TANH + EX2 + LG2) instead of 6, no RCP, fewer FMAs.

#define HW_   (1024u * 1024u)
#define B_    16u
#define PIX_  (B_ * HW_)        // 16,777,216 pixels
#define NVEC_ (PIX_ / 4u)       // float4 iterations

constexpr int BLOCKS  = 888;    // 148 SMs * 6 resident blocks = one wave
constexpr int THREADS = 256;

__device__ float g_part1[BLOCKS];
__device__ float g_part2[BLOCKS];
__device__ unsigned int g_ticket;   // zero-init at load; last block wraps it back to 0

__device__ __forceinline__ float tanh_fast(float x) {
    float r;
    asm("tanh.approx.f32 %0, %1;" : "=f"(r) : "f"(x));   // MUFU.TANH
    return r;
}
__device__ __forceinline__ float ex2_fast(float x) {
    float r;
    asm("ex2.approx.f32 %0, %1;" : "=f"(r) : "f"(x));    // MUFU.EX2
    return r;
}
__device__ __forceinline__ float lg2_fast(float x) {
    float r;
    asm("lg2.approx.f32 %0, %1;" : "=f"(r) : "f"(x));    // MUFU.LG2
    return r;
}

__device__ __forceinline__ float per_elem(float x0, float x1, float t0, float t1) {
    float a0 = tanh_fast(0.5f * x0);
    float a1 = tanh_fast(0.5f * x1);
    float d  = 0.5f * (a1 - a0);                         // sigmoid(x1)-sigmoid(x0), in (-1,1)
    // softplus(d) = ln(1 + e^d) = lg2(1 + 2^(d*log2e)) * ln2
    float e  = ex2_fast(d * 1.44269504f);
    float sp = lg2_fast(1.0f + e) * 0.69314718f;
    return (t0 + t1) * sp - t1 * d;
}

__device__ __forceinline__ float4 ldcs4(const float* p) {
    return __ldcs(reinterpret_cast<const float4*>(p));
}

__global__ __launch_bounds__(THREADS, 6) void xyloss_fused(
    const float* __restrict__ mask,
    const float* __restrict__ scale,
    const float* __restrict__ pred,
    const float* __restrict__ truth,
    float* __restrict__ out)
{
    float acc1 = 0.0f;
    float acc2 = 0.0f;

    const unsigned int stride = (unsigned int)(gridDim.x * blockDim.x);
    #pragma unroll 2
    for (unsigned int v = blockIdx.x * blockDim.x + threadIdx.x; v < NVEC_; v += stride) {
        unsigned int idx  = v << 2;                       // pixel index (multiple of 4)
        unsigned int base = idx + (idx & ~(HW_ - 1u));    // = idx + b*HW_

        // Front-batch ALL loads so they are in flight together.
        float4 m  = ldcs4(mask  + idx);
        float4 sc = ldcs4(scale + idx);
        float4 x0 = ldcs4(pred  + base);
        float4 x1 = ldcs4(pred  + base + HW_);
        float4 t0 = ldcs4(truth + base);
        float4 t1 = ldcs4(truth + base + HW_);

        acc2 += m.x * sc.x + m.y * sc.y + m.z * sc.z + m.w * sc.w;

        acc1 += per_elem(x0.x, x1.x, t0.x, t1.x);
        acc1 += per_elem(x0.y, x1.y, t0.y, t1.y);
        acc1 += per_elem(x0.z, x1.z, t0.z, t1.z);
        acc1 += per_elem(x0.w, x1.w, t0.w, t1.w);
    }

    // Warp reduce
    #pragma unroll
    for (int off = 16; off > 0; off >>= 1) {
        acc1 += __shfl_xor_sync(0xFFFFFFFFu, acc1, off);
        acc2 += __shfl_xor_sync(0xFFFFFFFFu, acc2, off);
    }

    // Block reduce across 8 warps
    __shared__ float sh1[THREADS / 32];
    __shared__ float sh2[THREADS / 32];
    __shared__ bool  s_last;
    int wid = threadIdx.x >> 5;
    int lid = threadIdx.x & 31;
    if (lid == 0) { sh1[wid] = acc1; sh2[wid] = acc2; }
    __syncthreads();
    if (threadIdx.x == 0) {
        float b1 = 0.0f, b2 = 0.0f;
        #pragma unroll
        for (int w = 0; w < THREADS / 32; w++) { b1 += sh1[w]; b2 += sh2[w]; }
        g_part1[blockIdx.x] = b1;
        g_part2[blockIdx.x] = b2;
        __threadfence();
        unsigned int t = atomicInc(&g_ticket, BLOCKS - 1);   // wraps to 0 at BLOCKS-1
        s_last = (t == BLOCKS - 1);                          // last arriving block; counter reset
    }
    __syncthreads();

    if (s_last) {
        // Deterministic double-precision combine of all BLOCKS partials.
        double a = 0.0, b = 0.0;
        for (int i = threadIdx.x; i < BLOCKS; i += THREADS) {
            a += (double)g_part1[i];
            b += (double)g_part2[i];
        }
        #pragma unroll
        for (int off = 16; off > 0; off >>= 1) {
            a += __shfl_xor_sync(0xFFFFFFFFu, a, off);
            b += __shfl_xor_sync(0xFFFFFFFFu, b, off);
        }
        __shared__ double da[THREADS / 32];
        __shared__ double db[THREADS / 32];
        if (lid == 0) { da[wid] = a; db[wid] = b; }
        __syncthreads();
        if (threadIdx.x == 0) {
            double A = 0.0, Bb = 0.0;
            #pragma unroll
            for (int w = 0; w < THREADS / 32; w++) { A += da[w]; Bb += db[w]; }
            double loss = A / (double)PIX_;
            out[0] = (float)(loss * Bb);
        }
    }
}

extern "C" void kernel_launch(void* const* d_in, const int* in_sizes, int n_in,
                              void* d_out, int out_size)
{
    const float* mask  = (const float*)d_in[0];
    const float* scale = (const float*)d_in[1];
    const float* pred  = (const float*)d_in[2];
    const float* truth = (const float*)d_in[3];
    float* out = (float*)d_out;

    xyloss_fused<<<BLOCKS, THREADS>>>(mask, scale, pred, truth, out);
}